// round 14
// baseline (speedup 1.0000x reference)
#include <cuda_runtime.h>
#include <cuda_bf16.h>
#include <cstdint>
#include <cfloat>

#define VOCAB   500000
#define EMB_D   128
#define HID     128
#define STEPS   64
#define NTILES  3907          // ceil(VOCAB/128)
#define K2CTAS  148

// ---------------- device globals (scratch; no allocation allowed) ----------
__device__ float               g_cs[STEPS * HID];    // cell states [step][k]
__device__ unsigned long long  g_best[STEPS];        // (enc(score)<<32)|~idx
__device__ int                 g_done = 0;           // k2 last-CTA counter

// ---------------- helpers ---------------------------------------------------
__device__ __forceinline__ uint32_t enc_f32(float f) {
    uint32_t u = __float_as_uint(f);
    return (u & 0x80000000u) ? ~u : (u | 0x80000000u);
}
__device__ __forceinline__ uint32_t smem_u32(const void* p) {
    return (uint32_t)__cvta_generic_to_shared(p);
}
__device__ __forceinline__ uint32_t mapa_rank(uint32_t local, uint32_t rank) {
    uint32_t r;
    asm volatile("mapa.shared::cluster.u32 %0, %1, %2;" : "=r"(r) : "r"(local), "r"(rank));
    return r;
}
__device__ __forceinline__ uint32_t my_cluster_rank() {
    uint32_t r; asm("mov.u32 %0, %%cluster_ctarank;" : "=r"(r)); return r;
}
__device__ __forceinline__ void cluster_sync_all() {
    asm volatile("barrier.cluster.arrive.aligned;" ::: "memory");
    asm volatile("barrier.cluster.wait.aligned;"   ::: "memory");
}
// fast activations (MUFU-based, ~1e-6 rel err; overflow-safe)
__device__ __forceinline__ float sig_fast(float x) {
    return __fdividef(1.0f, 1.0f + __expf(-x));
}
__device__ __forceinline__ float tanh_fast(float x) {
    return 1.0f - __fdividef(2.0f, __expf(2.0f * x) + 1.0f);
}
// split a float2 into bf16x2 hi and bf16x2 lo(residual)
__device__ __forceinline__ void split2(float2 v, uint32_t& hi, uint32_t& lo) {
    __nv_bfloat162 h = __floats2bfloat162_rn(v.x, v.y);
    hi = *(uint32_t*)&h;
    float rx = v.x - __bfloat162float(h.x);
    float ry = v.y - __bfloat162float(h.y);
    __nv_bfloat162 l = __floats2bfloat162_rn(rx, ry);
    lo = *(uint32_t*)&l;
}
// m16n8k16 row.col f32.bf16.bf16.f32
__device__ __forceinline__ void mma16816(float* c, const uint32_t* a,
                                         uint32_t b0, uint32_t b1) {
    asm volatile(
        "mma.sync.aligned.m16n8k16.row.col.f32.bf16.bf16.f32 "
        "{%0,%1,%2,%3}, {%4,%5,%6,%7}, {%8,%9}, {%0,%1,%2,%3};"
        : "+f"(c[0]), "+f"(c[1]), "+f"(c[2]), "+f"(c[3])
        : "r"(a[0]), "r"(a[1]), "r"(a[2]), "r"(a[3]), "r"(b0), "r"(b1));
}

// ============================================================================
// K1: 64 LSTM steps (cluster of 8 CTAs x 256 threads) — R8 version verbatim
//     (best measured k1: ~133us). barrier.cluster handoff; MUFU activations;
//     one __syncthreads/step; 32 sender threads x 4 remote b64 stores.
// ============================================================================
__global__ void __launch_bounds__(256, 1)
k1_lstm(const float* __restrict__ embed,
        const float* __restrict__ w_ih,
        const float* __restrict__ w_hh,
        const float* __restrict__ inp,
        const float* __restrict__ b_ih,
        const float* __restrict__ b_hh,
        float* __restrict__ out, int write_cs) {
    __shared__ float xh[2][256];
    __shared__ float gates_sm[64];
    __shared__ float Ksm[64];
    __shared__ float inp_sm[128];
    __shared__ alignas(8) float stage[32];          // [c x16 | h x16]

    const int tid  = threadIdx.x;
    const uint32_t rank = my_cluster_rank();

    const int lr   = tid >> 2;          // local gate row 0..63
    const int part = tid & 3;           // column quarter
    const int g    = lr >> 4;           // gate 0..3
    const int jj   = lr & 15;           // local hidden idx
    const int j    = (int)rank * 16 + jj;
    const int grow = g * 128 + j;       // global gate row

    if (rank == 0 && tid < STEPS) g_best[tid] = 0ull;

    if (tid < 128) {
        inp_sm[tid]      = inp[tid];
        xh[0][tid]       = embed[tid];
        xh[0][128 + tid] = 0.f;
    }

    float w[64];
    #pragma unroll
    for (int cc = 0; cc < 64; ++cc) {
        int col = part * 64 + cc;
        w[cc] = (col < 128) ? w_ih[grow * 256 + col]
                            : w_hh[grow * 128 + (col - 128)];
    }

    // hoisted sender addresses: thread tid<32 -> dest rank = tid>>2,
    // owns u64 pairs jj4..jj4+3 of the 16-u64 state block (0-7 = c, 8-15 = h)
    uint32_t rbase[2];
    const int jj4 = (tid & 3) * 4;
    if (tid < 32) {
        uint32_t dr = (uint32_t)(tid >> 2);
        #pragma unroll
        for (int pn = 0; pn < 2; ++pn) {
            uint32_t base = (jj4 < 8)
                ? smem_u32(&xh[pn][(int)rank * 16]) + 8u * jj4
                : smem_u32(&xh[pn][128 + (int)rank * 16]) + 8u * (jj4 - 8);
            rbase[pn] = mapa_rank(base, dr);
        }
    }
    __syncthreads();

    // fold K[grow] = b_ih + b_hh + W_ih[:,128:] @ inp
    {
        const float* wr = w_ih + grow * 256 + 128 + part * 32;
        float s = 0.f;
        #pragma unroll 8
        for (int c = 0; c < 32; ++c) s = fmaf(wr[c], inp_sm[part * 32 + c], s);
        s += __shfl_xor_sync(0xffffffffu, s, 1);
        s += __shfl_xor_sync(0xffffffffu, s, 2);
        if (part == 0) Ksm[lr] = s + b_ih[grow] + b_hh[grow];
    }
    __syncthreads();

    float c_reg = 0.f, k0v = 0.f, k1v = 0.f, k2v = 0.f, k3v = 0.f;
    if (tid < 16) {
        k0v = Ksm[ 0 + tid]; k1v = Ksm[16 + tid];
        k2v = Ksm[32 + tid]; k3v = Ksm[48 + tid];
    }
    __syncthreads();
    cluster_sync_all();     // xh[0] initialized in every CTA

    for (int step = 0; step < STEPS; ++step) {
        const int p = step & 1;
        const float4* xv = (const float4*)&xh[p][part * 64];
        float a0 = 0.f, a1 = 0.f, a2 = 0.f, a3 = 0.f;
        #pragma unroll
        for (int qq = 0; qq < 16; ++qq) {
            float4 v = xv[qq];
            a0 = fmaf(w[4*qq + 0], v.x, a0);
            a1 = fmaf(w[4*qq + 1], v.y, a1);
            a2 = fmaf(w[4*qq + 2], v.z, a2);
            a3 = fmaf(w[4*qq + 3], v.w, a3);
        }
        float acc = (a0 + a1) + (a2 + a3);
        acc += __shfl_xor_sync(0xffffffffu, acc, 1);
        acc += __shfl_xor_sync(0xffffffffu, acc, 2);
        if (part == 0) gates_sm[lr] = acc;
        __syncthreads();          // the only block barrier per step

        if (tid < 32) {           // warp 0: epilogue + senders
            if (tid < 16) {
                int je = (int)rank * 16 + tid;
                float gi = gates_sm[ 0 + tid] + k0v;
                float gf = gates_sm[16 + tid] + k1v;
                float gg = gates_sm[32 + tid] + k2v;
                float go = gates_sm[48 + tid] + k3v;
                float iv = sig_fast(gi), fv = sig_fast(gf);
                float gv = tanh_fast(gg), ov = sig_fast(go);
                float c_new = fv * c_reg + iv * gv;
                float h_new = ov * tanh_fast(c_new);
                c_reg = c_new;
                if (write_cs) out[step * 128 + je] = c_new;
                g_cs[step * 128 + je] = c_new;
                stage[tid]      = c_new;
                stage[16 + tid] = h_new;
            }
            __syncwarp();
            if (step < STEPS - 1) {
                const unsigned long long* sg = (const unsigned long long*)stage;
                uint32_t rb = rbase[p ^ 1];
                #pragma unroll
                for (int i = 0; i < 4; ++i) {
                    asm volatile("st.shared::cluster.b64 [%0], %1;"
                                 :: "r"(rb + 8u * i), "l"(sg[jj4 + i]) : "memory");
                }
            }
        }
        // HW cluster barrier: releases warp0's remote stores, acquires peers'
        cluster_sync_all();
    }
}

// ============================================================================
// K2v2: persistent scorer, 148 CTAs x 512 threads (16 warps = 4/SMSP).
//     Tile 128 rows x 64 steps. Warp w<8: row-frag w, steps 0-31;
//     warp w>=8: row-frag w-8, steps 32-63. Split-at-load (no F buffer)
//     keeps regs <= 128 so all 16 warps fit at occupancy 1.
// ============================================================================
__global__ void __launch_bounds__(512, 1)
k2_score(const float* __restrict__ embed, float* __restrict__ out, int out_size) {
    __shared__ uint4 sbfrag[2048];                  // [nc*8+kc][lane], 32KB
    __shared__ unsigned long long wb[16][32];       // [warp][local step]
    __shared__ int is_last;

    const int tid  = threadIdx.x;
    const int lane = tid & 31;
    const int w    = tid >> 5;          // 0..15
    const int q    = lane & 3;          // col-quad within fragment
    const int r4   = lane >> 2;         // fragment row 0..7
    const int wf   = w & 7;             // row-fragment id 0..7
    const int sh   = (w >> 3) * 4;      // nc offset: 0 or 4 (steps 0-31 / 32-63)

    // ---- build B fragments from g_cs into smem (once per CTA) ----
    {
        const float2* c2 = (const float2*)g_cs;
        #pragma unroll
        for (int it = 0; it < 4; ++it) {
            int idx  = tid + it * 512;
            int ln   = idx & 31;
            int kc   = (idx >> 5) & 7;
            int nc   = idx >> 8;
            int n    = nc * 8 + (ln >> 2);
            int qq   = ln & 3;
            float2 p01 = c2[n * 64 + kc * 8 + qq];
            float2 p23 = c2[n * 64 + kc * 8 + qq + 4];
            uint32_t h01, l01, h23, l23;
            split2(p01, h01, l01);
            split2(p23, h23, l23);
            sbfrag[idx] = make_uint4(h01, h23, l01, l23);
        }
    }
    __syncthreads();

    const float2* e2 = (const float2*)embed;
    const float2 z2 = make_float2(0.f, 0.f);

    // running best per (nc,e) slot: slot = nc*2+e, local step = nc*8+2q+e
    float bs[8]; int br[8];
    #pragma unroll
    for (int i = 0; i < 8; ++i) { bs[i] = -FLT_MAX; br[i] = 0; }

    for (int t = blockIdx.x; t < NTILES; t += K2CTAS) {
        const int  row0 = t * 128 + wf * 16 + r4;
        const int  row1 = row0 + 8;
        const bool v0 = row0 < VOCAB, v1 = row1 < VOCAB;

        // ---- load A rows + split at load (no raw buffer) + ssq ----
        uint32_t aH[8][4], aL[8][4];
        float ssq0 = 0.f, ssq1 = 0.f;
        {
            size_t b0 = (size_t)(v0 ? row0 : 0) * 64;
            size_t b1 = (size_t)(v1 ? row1 : 0) * 64;
            #pragma unroll
            for (int kc = 0; kc < 8; ++kc) {
                float2 f00 = v0 ? e2[b0 + kc * 8 + q]     : z2;
                float2 f01 = v0 ? e2[b0 + kc * 8 + q + 4] : z2;
                float2 f10 = v1 ? e2[b1 + kc * 8 + q]     : z2;
                float2 f11 = v1 ? e2[b1 + kc * 8 + q + 4] : z2;
                ssq0 = fmaf(f00.x, f00.x, fmaf(f00.y, f00.y,
                        fmaf(f01.x, f01.x, fmaf(f01.y, f01.y, ssq0))));
                ssq1 = fmaf(f10.x, f10.x, fmaf(f10.y, f10.y,
                        fmaf(f11.x, f11.x, fmaf(f11.y, f11.y, ssq1))));
                split2(f00, aH[kc][0], aL[kc][0]);
                split2(f10, aH[kc][1], aL[kc][1]);
                split2(f01, aH[kc][2], aL[kc][2]);
                split2(f11, aH[kc][3], aL[kc][3]);
            }
        }
        ssq0 += __shfl_xor_sync(0xffffffffu, ssq0, 1);
        ssq0 += __shfl_xor_sync(0xffffffffu, ssq0, 2);
        ssq1 += __shfl_xor_sync(0xffffffffu, ssq1, 1);
        ssq1 += __shfl_xor_sync(0xffffffffu, ssq1, 2);
        const float iv0 = 1.0f / fmaxf(sqrtf(ssq0), 1e-8f);
        const float iv1 = 1.0f / fmaxf(sqrtf(ssq1), 1e-8f);

        // ---- MMA over this warp's 4 nc groups + running argmax ----
        #pragma unroll
        for (int nc = 0; nc < 4; ++nc) {
            float c1[4]  = {0.f, 0.f, 0.f, 0.f};
            float c2a[4] = {0.f, 0.f, 0.f, 0.f};
            float c3[4]  = {0.f, 0.f, 0.f, 0.f};
            #pragma unroll
            for (int kc = 0; kc < 8; ++kc) {
                uint4 bb = sbfrag[((sh + nc) * 8 + kc) * 32 + lane];
                mma16816(c1,  aH[kc], bb.x, bb.y);   // hi*hi
                mma16816(c2a, aH[kc], bb.z, bb.w);   // hi*lo
                mma16816(c3,  aL[kc], bb.x, bb.y);   // lo*hi
            }
            #pragma unroll
            for (int e = 0; e < 2; ++e) {
                const int sl = nc * 2 + e;
                float s0 = v0 ? (c1[e]     + c2a[e]     + c3[e])     * iv0 : -FLT_MAX;
                float s1 = v1 ? (c1[2 + e] + c2a[2 + e] + c3[2 + e]) * iv1 : -FLT_MAX;
                if (s0 > bs[sl]) { bs[sl] = s0; br[sl] = row0; }  // row0 first:
                if (s1 > bs[sl]) { bs[sl] = s1; br[sl] = row1; }  // first-max wins
            }
        }
        // no barrier: warps free-run across tiles (sbfrag is read-only)
    }

    // ---- single final reduction ----
    #pragma unroll
    for (int sl = 0; sl < 8; ++sl) {
        unsigned long long key =
            ((unsigned long long)enc_f32(bs[sl]) << 32) |
            (uint32_t)(~(uint32_t)br[sl]);
        #pragma unroll
        for (int off = 4; off < 32; off <<= 1) {
            unsigned long long o = __shfl_xor_sync(0xffffffffu, key, off);
            if (o > key) key = o;
        }
        if (r4 == 0) wb[w][(sl >> 1) * 8 + 2 * q + (sl & 1)] = key;  // lanes 0..3
    }
    __syncthreads();
    if (tid < STEPS) {
        const int s  = tid;
        const int g0 = (s >= 32) ? 8 : 0;       // which warp group owns step s
        const int ls = s & 31;
        unsigned long long best = wb[g0][ls];
        #pragma unroll
        for (int ww = 1; ww < 8; ++ww)
            if (wb[g0 + ww][ls] > best) best = wb[g0 + ww][ls];
        atomicMax(&g_best[s], best);
    }

    // ---- last CTA decodes token ids ----
    __threadfence();
    __syncthreads();
    if (tid == 0) {
        int c = atomicAdd(&g_done, 1);
        is_last = (c == (int)gridDim.x - 1);
    }
    __syncthreads();
    if (is_last) {
        if (tid == 0) g_done = 0;
        __threadfence();
        if (tid < STEPS) {
            uint32_t idx = ~((uint32_t)(g_best[tid] & 0xffffffffu));
            out[(out_size - STEPS) + tid] = (float)idx;
        }
    }
}

// ============================================================================
extern "C" void kernel_launch(void* const* d_in, const int* in_sizes, int n_in,
                              void* d_out, int out_size) {
    const float* inp   = (const float*)d_in[0];
    const float* embed = (const float*)d_in[1];
    const float* w_ih  = (const float*)d_in[2];
    const float* w_hh  = (const float*)d_in[3];
    const float* b_ih  = (const float*)d_in[4];
    const float* b_hh  = (const float*)d_in[5];
    float* out = (float*)d_out;
    (void)in_sizes; (void)n_in;

    const int write_cs = (out_size >= STEPS * 128 + STEPS) ? 1 : 0;

    // Phase A: cluster-of-8 LSTM (best measured variant, R8)
    {
        cudaLaunchConfig_t cfg = {};
        cfg.gridDim  = dim3(8, 1, 1);
        cfg.blockDim = dim3(256, 1, 1);
        cfg.dynamicSmemBytes = 0;
        cfg.stream = 0;
        cudaLaunchAttribute attrs[1];
        attrs[0].id = cudaLaunchAttributeClusterDimension;
        attrs[0].val.clusterDim.x = 8;
        attrs[0].val.clusterDim.y = 1;
        attrs[0].val.clusterDim.z = 1;
        cfg.attrs = attrs;
        cfg.numAttrs = 1;
        cudaLaunchKernelEx(&cfg, k1_lstm, embed, w_ih, w_hh, inp, b_ih, b_hh,
                           out, write_cs);
    }

    // Phase B: 512-thread persistent mma.sync scoring + argmax + decode
    k2_score<<<K2CTAS, 512>>>(embed, out, out_size);
}

// round 15
// speedup vs baseline: 1.1346x; 1.1346x over previous
#include <cuda_runtime.h>
#include <cuda_bf16.h>
#include <cstdint>
#include <cfloat>

#define VOCAB   500000
#define EMB_D   128
#define HID     128
#define STEPS   64
#define TILE_R  192
#define NTILES2 2605          // ceil(VOCAB/192)
#define K2CTAS  148

// ---------------- device globals (scratch; no allocation allowed) ----------
__device__ float               g_cs[STEPS * HID];    // cell states [step][k]
__device__ unsigned long long  g_best[STEPS];        // (enc(score)<<32)|~idx
__device__ int                 g_done = 0;           // k2 last-CTA counter

// ---------------- helpers ---------------------------------------------------
__device__ __forceinline__ uint32_t enc_f32(float f) {
    uint32_t u = __float_as_uint(f);
    return (u & 0x80000000u) ? ~u : (u | 0x80000000u);
}
__device__ __forceinline__ uint32_t smem_u32(const void* p) {
    return (uint32_t)__cvta_generic_to_shared(p);
}
__device__ __forceinline__ uint32_t mapa_rank(uint32_t local, uint32_t rank) {
    uint32_t r;
    asm volatile("mapa.shared::cluster.u32 %0, %1, %2;" : "=r"(r) : "r"(local), "r"(rank));
    return r;
}
__device__ __forceinline__ uint32_t my_cluster_rank() {
    uint32_t r; asm("mov.u32 %0, %%cluster_ctarank;" : "=r"(r)); return r;
}
__device__ __forceinline__ void cluster_sync_all() {
    asm volatile("barrier.cluster.arrive.aligned;" ::: "memory");
    asm volatile("barrier.cluster.wait.aligned;"   ::: "memory");
}
// fast activations (MUFU-based, ~1e-6 rel err; overflow-safe)
__device__ __forceinline__ float sig_fast(float x) {
    return __fdividef(1.0f, 1.0f + __expf(-x));
}
__device__ __forceinline__ float tanh_fast(float x) {
    return 1.0f - __fdividef(2.0f, __expf(2.0f * x) + 1.0f);
}
// split a float2 into bf16x2 hi and bf16x2 lo(residual)
__device__ __forceinline__ void split2(float2 v, uint32_t& hi, uint32_t& lo) {
    __nv_bfloat162 h = __floats2bfloat162_rn(v.x, v.y);
    hi = *(uint32_t*)&h;
    float rx = v.x - __bfloat162float(h.x);
    float ry = v.y - __bfloat162float(h.y);
    __nv_bfloat162 l = __floats2bfloat162_rn(rx, ry);
    lo = *(uint32_t*)&l;
}
// m16n8k16 row.col f32.bf16.bf16.f32
__device__ __forceinline__ void mma16816(float* c, const uint32_t* a,
                                         uint32_t b0, uint32_t b1) {
    asm volatile(
        "mma.sync.aligned.m16n8k16.row.col.f32.bf16.bf16.f32 "
        "{%0,%1,%2,%3}, {%4,%5,%6,%7}, {%8,%9}, {%0,%1,%2,%3};"
        : "+f"(c[0]), "+f"(c[1]), "+f"(c[2]), "+f"(c[3])
        : "r"(a[0]), "r"(a[1]), "r"(a[2]), "r"(a[3]), "r"(b0), "r"(b1));
}

// ============================================================================
// K1: 64 LSTM steps (cluster of 8 CTAs x 256 threads) — R8 version verbatim
//     (best measured k1: ~133us across 6 sync-mechanism variants).
// ============================================================================
__global__ void __launch_bounds__(256, 1)
k1_lstm(const float* __restrict__ embed,
        const float* __restrict__ w_ih,
        const float* __restrict__ w_hh,
        const float* __restrict__ inp,
        const float* __restrict__ b_ih,
        const float* __restrict__ b_hh,
        float* __restrict__ out, int write_cs) {
    __shared__ float xh[2][256];
    __shared__ float gates_sm[64];
    __shared__ float Ksm[64];
    __shared__ float inp_sm[128];
    __shared__ alignas(8) float stage[32];          // [c x16 | h x16]

    const int tid  = threadIdx.x;
    const uint32_t rank = my_cluster_rank();

    const int lr   = tid >> 2;          // local gate row 0..63
    const int part = tid & 3;           // column quarter
    const int g    = lr >> 4;           // gate 0..3
    const int jj   = lr & 15;           // local hidden idx
    const int j    = (int)rank * 16 + jj;
    const int grow = g * 128 + j;       // global gate row

    if (rank == 0 && tid < STEPS) g_best[tid] = 0ull;

    if (tid < 128) {
        inp_sm[tid]      = inp[tid];
        xh[0][tid]       = embed[tid];
        xh[0][128 + tid] = 0.f;
    }

    float w[64];
    #pragma unroll
    for (int cc = 0; cc < 64; ++cc) {
        int col = part * 64 + cc;
        w[cc] = (col < 128) ? w_ih[grow * 256 + col]
                            : w_hh[grow * 128 + (col - 128)];
    }

    // hoisted sender addresses: thread tid<32 -> dest rank = tid>>2,
    // owns u64 pairs jj4..jj4+3 of the 16-u64 state block (0-7 = c, 8-15 = h)
    uint32_t rbase[2];
    const int jj4 = (tid & 3) * 4;
    if (tid < 32) {
        uint32_t dr = (uint32_t)(tid >> 2);
        #pragma unroll
        for (int pn = 0; pn < 2; ++pn) {
            uint32_t base = (jj4 < 8)
                ? smem_u32(&xh[pn][(int)rank * 16]) + 8u * jj4
                : smem_u32(&xh[pn][128 + (int)rank * 16]) + 8u * (jj4 - 8);
            rbase[pn] = mapa_rank(base, dr);
        }
    }
    __syncthreads();

    // fold K[grow] = b_ih + b_hh + W_ih[:,128:] @ inp
    {
        const float* wr = w_ih + grow * 256 + 128 + part * 32;
        float s = 0.f;
        #pragma unroll 8
        for (int c = 0; c < 32; ++c) s = fmaf(wr[c], inp_sm[part * 32 + c], s);
        s += __shfl_xor_sync(0xffffffffu, s, 1);
        s += __shfl_xor_sync(0xffffffffu, s, 2);
        if (part == 0) Ksm[lr] = s + b_ih[grow] + b_hh[grow];
    }
    __syncthreads();

    float c_reg = 0.f, k0v = 0.f, k1v = 0.f, k2v = 0.f, k3v = 0.f;
    if (tid < 16) {
        k0v = Ksm[ 0 + tid]; k1v = Ksm[16 + tid];
        k2v = Ksm[32 + tid]; k3v = Ksm[48 + tid];
    }
    __syncthreads();
    cluster_sync_all();     // xh[0] initialized in every CTA

    for (int step = 0; step < STEPS; ++step) {
        const int p = step & 1;
        const float4* xv = (const float4*)&xh[p][part * 64];
        float a0 = 0.f, a1 = 0.f, a2 = 0.f, a3 = 0.f;
        #pragma unroll
        for (int qq = 0; qq < 16; ++qq) {
            float4 v = xv[qq];
            a0 = fmaf(w[4*qq + 0], v.x, a0);
            a1 = fmaf(w[4*qq + 1], v.y, a1);
            a2 = fmaf(w[4*qq + 2], v.z, a2);
            a3 = fmaf(w[4*qq + 3], v.w, a3);
        }
        float acc = (a0 + a1) + (a2 + a3);
        acc += __shfl_xor_sync(0xffffffffu, acc, 1);
        acc += __shfl_xor_sync(0xffffffffu, acc, 2);
        if (part == 0) gates_sm[lr] = acc;
        __syncthreads();          // the only block barrier per step

        if (tid < 32) {           // warp 0: epilogue + senders
            if (tid < 16) {
                int je = (int)rank * 16 + tid;
                float gi = gates_sm[ 0 + tid] + k0v;
                float gf = gates_sm[16 + tid] + k1v;
                float gg = gates_sm[32 + tid] + k2v;
                float go = gates_sm[48 + tid] + k3v;
                float iv = sig_fast(gi), fv = sig_fast(gf);
                float gv = tanh_fast(gg), ov = sig_fast(go);
                float c_new = fv * c_reg + iv * gv;
                float h_new = ov * tanh_fast(c_new);
                c_reg = c_new;
                if (write_cs) out[step * 128 + je] = c_new;
                g_cs[step * 128 + je] = c_new;
                stage[tid]      = c_new;
                stage[16 + tid] = h_new;
            }
            __syncwarp();
            if (step < STEPS - 1) {
                const unsigned long long* sg = (const unsigned long long*)stage;
                uint32_t rb = rbase[p ^ 1];
                #pragma unroll
                for (int i = 0; i < 4; ++i) {
                    asm volatile("st.shared::cluster.b64 [%0], %1;"
                                 :: "r"(rb + 8u * i), "l"(sg[jj4 + i]) : "memory");
                }
            }
        }
        // HW cluster barrier: releases warp0's remote stores, acquires peers'
        cluster_sync_all();
    }
}

// ============================================================================
// K2v3: persistent scorer, 148 CTAs x 384 threads (12 warps = 3/SMSP).
//     Tile 192 rows x 64 steps; warp w owns rows w*16..w*16+15, ALL 64 steps
//     (8 nc, 24 MMAs per tile — R8's MMA:load ratio). Split-at-load, regs
//     ~135 < 170 cap: no spills. Cross-warp latency hiding (3 warps/SMSP).
// ============================================================================
__global__ void __launch_bounds__(384, 1)
k2_score(const float* __restrict__ embed, float* __restrict__ out, int out_size) {
    __shared__ uint4 sbfrag[2048];                  // [nc*8+kc][lane], 32KB
    __shared__ unsigned long long wb[12][STEPS];    // [warp][step], 6KB
    __shared__ int is_last;

    const int tid  = threadIdx.x;
    const int lane = tid & 31;
    const int w    = tid >> 5;          // 0..11
    const int q    = lane & 3;          // col-quad within fragment
    const int r4   = lane >> 2;         // fragment row 0..7

    // ---- build B fragments from g_cs into smem (once per CTA) ----
    {
        const float2* c2 = (const float2*)g_cs;
        for (int idx = tid; idx < 2048; idx += 384) {
            int ln   = idx & 31;
            int kc   = (idx >> 5) & 7;
            int nc   = idx >> 8;
            int n    = nc * 8 + (ln >> 2);
            int qq   = ln & 3;
            float2 p01 = c2[n * 64 + kc * 8 + qq];
            float2 p23 = c2[n * 64 + kc * 8 + qq + 4];
            uint32_t h01, l01, h23, l23;
            split2(p01, h01, l01);
            split2(p23, h23, l23);
            sbfrag[idx] = make_uint4(h01, h23, l01, l23);
        }
    }
    __syncthreads();

    const float2* e2 = (const float2*)embed;
    const float2 z2 = make_float2(0.f, 0.f);

    // running best per (nc,e) slot: slot = nc*2+e  <->  step = nc*8+2q+e
    float bs[16]; int br[16];
    #pragma unroll
    for (int i = 0; i < 16; ++i) { bs[i] = -FLT_MAX; br[i] = 0; }

    for (int t = blockIdx.x; t < NTILES2; t += K2CTAS) {
        const int  row0 = t * TILE_R + w * 16 + r4;
        const int  row1 = row0 + 8;
        const bool v0 = row0 < VOCAB, v1 = row1 < VOCAB;

        // ---- load A rows + split at load + row ssq ----
        uint32_t aH[8][4], aL[8][4];
        float ssq0 = 0.f, ssq1 = 0.f;
        {
            size_t b0 = (size_t)(v0 ? row0 : 0) * 64;
            size_t b1 = (size_t)(v1 ? row1 : 0) * 64;
            #pragma unroll
            for (int kc = 0; kc < 8; ++kc) {
                float2 f00 = v0 ? e2[b0 + kc * 8 + q]     : z2;
                float2 f01 = v0 ? e2[b0 + kc * 8 + q + 4] : z2;
                float2 f10 = v1 ? e2[b1 + kc * 8 + q]     : z2;
                float2 f11 = v1 ? e2[b1 + kc * 8 + q + 4] : z2;
                ssq0 = fmaf(f00.x, f00.x, fmaf(f00.y, f00.y,
                        fmaf(f01.x, f01.x, fmaf(f01.y, f01.y, ssq0))));
                ssq1 = fmaf(f10.x, f10.x, fmaf(f10.y, f10.y,
                        fmaf(f11.x, f11.x, fmaf(f11.y, f11.y, ssq1))));
                split2(f00, aH[kc][0], aL[kc][0]);
                split2(f10, aH[kc][1], aL[kc][1]);
                split2(f01, aH[kc][2], aL[kc][2]);
                split2(f11, aH[kc][3], aL[kc][3]);
            }
        }
        ssq0 += __shfl_xor_sync(0xffffffffu, ssq0, 1);
        ssq0 += __shfl_xor_sync(0xffffffffu, ssq0, 2);
        ssq1 += __shfl_xor_sync(0xffffffffu, ssq1, 1);
        ssq1 += __shfl_xor_sync(0xffffffffu, ssq1, 2);
        const float iv0 = 1.0f / fmaxf(sqrtf(ssq0), 1e-8f);
        const float iv1 = 1.0f / fmaxf(sqrtf(ssq1), 1e-8f);

        // ---- MMA: all 8 nc groups + running register argmax ----
        #pragma unroll
        for (int nc = 0; nc < 8; ++nc) {
            float c1[4]  = {0.f, 0.f, 0.f, 0.f};
            float c2a[4] = {0.f, 0.f, 0.f, 0.f};
            float c3[4]  = {0.f, 0.f, 0.f, 0.f};
            #pragma unroll
            for (int kc = 0; kc < 8; ++kc) {
                uint4 bb = sbfrag[(nc * 8 + kc) * 32 + lane];
                mma16816(c1,  aH[kc], bb.x, bb.y);   // hi*hi
                mma16816(c2a, aH[kc], bb.z, bb.w);   // hi*lo
                mma16816(c3,  aL[kc], bb.x, bb.y);   // lo*hi
            }
            #pragma unroll
            for (int e = 0; e < 2; ++e) {
                const int sl = nc * 2 + e;
                float s0 = v0 ? (c1[e]     + c2a[e]     + c3[e])     * iv0 : -FLT_MAX;
                float s1 = v1 ? (c1[2 + e] + c2a[2 + e] + c3[2 + e]) * iv1 : -FLT_MAX;
                if (s0 > bs[sl]) { bs[sl] = s0; br[sl] = row0; }  // row0 first:
                if (s1 > bs[sl]) { bs[sl] = s1; br[sl] = row1; }  // first-max wins
            }
        }
        // no barrier: warps free-run across tiles (sbfrag is read-only)
    }

    // ---- single final reduction ----
    #pragma unroll
    for (int sl = 0; sl < 16; ++sl) {
        unsigned long long key =
            ((unsigned long long)enc_f32(bs[sl]) << 32) |
            (uint32_t)(~(uint32_t)br[sl]);
        #pragma unroll
        for (int off = 4; off < 32; off <<= 1) {
            unsigned long long o = __shfl_xor_sync(0xffffffffu, key, off);
            if (o > key) key = o;
        }
        if (r4 == 0) wb[w][(sl >> 1) * 8 + 2 * q + (sl & 1)] = key;  // lanes 0..3
    }
    __syncthreads();
    if (tid < STEPS) {
        unsigned long long best = wb[0][tid];
        #pragma unroll
        for (int ww = 1; ww < 12; ++ww)
            if (wb[ww][tid] > best) best = wb[ww][tid];
        atomicMax(&g_best[tid], best);
    }

    // ---- last CTA decodes token ids ----
    __threadfence();
    __syncthreads();
    if (tid == 0) {
        int c = atomicAdd(&g_done, 1);
        is_last = (c == (int)gridDim.x - 1);
    }
    __syncthreads();
    if (is_last) {
        if (tid == 0) g_done = 0;
        __threadfence();
        if (tid < STEPS) {
            uint32_t idx = ~((uint32_t)(g_best[tid] & 0xffffffffu));
            out[(out_size - STEPS) + tid] = (float)idx;
        }
    }
}

// ============================================================================
extern "C" void kernel_launch(void* const* d_in, const int* in_sizes, int n_in,
                              void* d_out, int out_size) {
    const float* inp   = (const float*)d_in[0];
    const float* embed = (const float*)d_in[1];
    const float* w_ih  = (const float*)d_in[2];
    const float* w_hh  = (const float*)d_in[3];
    const float* b_ih  = (const float*)d_in[4];
    const float* b_hh  = (const float*)d_in[5];
    float* out = (float*)d_out;
    (void)in_sizes; (void)n_in;

    const int write_cs = (out_size >= STEPS * 128 + STEPS) ? 1 : 0;

    // Phase A: cluster-of-8 LSTM (best measured variant, R8)
    {
        cudaLaunchConfig_t cfg = {};
        cfg.gridDim  = dim3(8, 1, 1);
        cfg.blockDim = dim3(256, 1, 1);
        cfg.dynamicSmemBytes = 0;
        cfg.stream = 0;
        cudaLaunchAttribute attrs[1];
        attrs[0].id = cudaLaunchAttributeClusterDimension;
        attrs[0].val.clusterDim.x = 8;
        attrs[0].val.clusterDim.y = 1;
        attrs[0].val.clusterDim.z = 1;
        cfg.attrs = attrs;
        cfg.numAttrs = 1;
        cudaLaunchKernelEx(&cfg, k1_lstm, embed, w_ih, w_hh, inp, b_ih, b_hh,
                           out, write_cs);
    }

    // Phase B: 384-thread persistent mma.sync scoring + argmax + decode
    k2_score<<<K2CTAS, 384>>>(embed, out, out_size);
}

// round 16
// speedup vs baseline: 1.7363x; 1.5303x over previous
#include <cuda_runtime.h>
#include <cuda_bf16.h>
#include <cstdint>
#include <cfloat>

#define VOCAB   500000
#define EMB_D   128
#define HID     128
#define STEPS   64
#define NTILES  3907          // ceil(VOCAB/128)
#define K2CTAS  148
#define XH_H    132           // padded h offset (bank-shift 4 vs c region)

// ---------------- device globals (scratch; no allocation allowed) ----------
__device__ float               g_cs[STEPS * HID];    // cell states [step][k]
__device__ unsigned long long  g_best[STEPS];        // (enc(score)<<32)|~idx
__device__ int                 g_done = 0;           // k2 last-CTA counter

// ---------------- helpers ---------------------------------------------------
__device__ __forceinline__ uint32_t enc_f32(float f) {
    uint32_t u = __float_as_uint(f);
    return (u & 0x80000000u) ? ~u : (u | 0x80000000u);
}
__device__ __forceinline__ uint32_t smem_u32(const void* p) {
    return (uint32_t)__cvta_generic_to_shared(p);
}
__device__ __forceinline__ uint32_t mapa_rank(uint32_t local, uint32_t rank) {
    uint32_t r;
    asm volatile("mapa.shared::cluster.u32 %0, %1, %2;" : "=r"(r) : "r"(local), "r"(rank));
    return r;
}
__device__ __forceinline__ uint32_t my_cluster_rank() {
    uint32_t r; asm("mov.u32 %0, %%cluster_ctarank;" : "=r"(r)); return r;
}
__device__ __forceinline__ void cluster_sync_all() {
    asm volatile("barrier.cluster.arrive.aligned;" ::: "memory");
    asm volatile("barrier.cluster.wait.aligned;"   ::: "memory");
}
// fast activations (MUFU-based, ~1e-6 rel err; overflow-safe)
__device__ __forceinline__ float sig_fast(float x) {
    return __fdividef(1.0f, 1.0f + __expf(-x));
}
__device__ __forceinline__ float tanh_fast(float x) {
    return 1.0f - __fdividef(2.0f, __expf(2.0f * x) + 1.0f);
}
// split a float2 into bf16x2 hi and bf16x2 lo(residual)
__device__ __forceinline__ void split2(float2 v, uint32_t& hi, uint32_t& lo) {
    __nv_bfloat162 h = __floats2bfloat162_rn(v.x, v.y);
    hi = *(uint32_t*)&h;
    float rx = v.x - __bfloat162float(h.x);
    float ry = v.y - __bfloat162float(h.y);
    __nv_bfloat162 l = __floats2bfloat162_rn(rx, ry);
    lo = *(uint32_t*)&l;
}
// m16n8k16 row.col f32.bf16.bf16.f32
__device__ __forceinline__ void mma16816(float* c, const uint32_t* a,
                                         uint32_t b0, uint32_t b1) {
    asm volatile(
        "mma.sync.aligned.m16n8k16.row.col.f32.bf16.bf16.f32 "
        "{%0,%1,%2,%3}, {%4,%5,%6,%7}, {%8,%9}, {%0,%1,%2,%3};"
        : "+f"(c[0]), "+f"(c[1]), "+f"(c[2]), "+f"(c[3])
        : "r"(a[0]), "r"(a[1]), "r"(a[2]), "r"(a[3]), "r"(b0), "r"(b1));
}

// ============================================================================
// K1: 64 LSTM steps, cluster of 4 CTAs x 256 threads.
//     CTA `rank` owns hidden j in [32r, 32r+32) -> 128 gate rows.
//     Thread (row=tid>>1, half=tid&1): 1 gate row x 128 cols, 128 weight regs.
//     Handoff = barrier.cluster (cheapest measured); 32 senders x 4 remote b64.
// ============================================================================
__global__ void __launch_bounds__(256, 1)
k1_lstm(const float* __restrict__ embed,
        const float* __restrict__ w_ih,
        const float* __restrict__ w_hh,
        const float* __restrict__ inp,
        const float* __restrict__ b_ih,
        const float* __restrict__ b_hh,
        float* __restrict__ out, int write_cs) {
    __shared__ float xh[2][264];        // c at [0,128), h at [132,260)
    __shared__ float gates_sm[128];     // row = g*32 + jloc
    __shared__ float Ksm[128];
    __shared__ float inp_sm[128];
    __shared__ alignas(8) float stage[64];   // [c x32 | h x32]

    const int tid  = threadIdx.x;
    const uint32_t rank = my_cluster_rank();

    const int row  = tid >> 1;          // gate row 0..127
    const int half = tid & 1;           // column half (128 cols)
    const int g    = row >> 5;          // gate 0..3
    const int jloc = row & 31;          // local hidden idx
    const int grow = g * 128 + 32 * (int)rank + jloc;  // global gate row

    if (rank == 0 && tid < STEPS) g_best[tid] = 0ull;

    if (tid < 128) {
        inp_sm[tid]          = inp[tid];
        xh[0][tid]           = embed[tid];   // x0 = embed[<start>=0]
        xh[0][XH_H + tid]    = 0.f;          // h0 = 0
    }

    // ---- weights: 1 row x 128 cols per thread (x-part or h-part) ----
    float w[128];
    {
        const float4* wp = (const float4*)(half ? (w_hh + grow * 128)
                                                : (w_ih + grow * 256));
        #pragma unroll
        for (int i = 0; i < 32; ++i) {
            float4 v = wp[i];
            w[4*i + 0] = v.x; w[4*i + 1] = v.y;
            w[4*i + 2] = v.z; w[4*i + 3] = v.w;
        }
    }

    // ---- hoisted sender addresses (warp 0 lanes; dest = all 4 ranks) ----
    uint32_t rbase[2][4];
    if (tid < 32) {
        #pragma unroll
        for (int pn = 0; pn < 2; ++pn) {
            uint32_t local = (tid < 16)
                ? smem_u32(&xh[pn][32 * (int)rank]) + 8u * tid
                : smem_u32(&xh[pn][XH_H + 32 * (int)rank]) + 8u * (tid - 16);
            #pragma unroll
            for (int r = 0; r < 4; ++r)
                rbase[pn][r] = mapa_rank(local, (uint32_t)r);
        }
    }
    __syncthreads();

    // ---- fold K[grow] = b_ih + b_hh + W_ih[:,128:] @ inp ----
    {
        const float* wr = w_ih + grow * 256 + 128 + half * 64;
        float s = 0.f;
        #pragma unroll 8
        for (int c = 0; c < 64; ++c) s = fmaf(wr[c], inp_sm[half * 64 + c], s);
        s += __shfl_xor_sync(0xffffffffu, s, 1);
        if (half == 0) Ksm[row] = s + b_ih[grow] + b_hh[grow];
    }
    __syncthreads();

    float c_reg = 0.f, k0v = 0.f, k1v = 0.f, k2v = 0.f, k3v = 0.f;
    if (tid < 32) {
        k0v = Ksm[tid];      k1v = Ksm[32 + tid];
        k2v = Ksm[64 + tid]; k3v = Ksm[96 + tid];
    }
    __syncthreads();
    cluster_sync_all();     // xh[0] initialized in every CTA

    for (int step = 0; step < STEPS; ++step) {
        const int p = step & 1;
        // ---- dot: 1 row x 128 cols per thread ----
        const float4* xv = (const float4*)&xh[p][half * XH_H];
        float a0 = 0.f, a1 = 0.f, a2 = 0.f, a3 = 0.f;
        #pragma unroll
        for (int qq = 0; qq < 32; ++qq) {
            float4 v = xv[qq];
            a0 = fmaf(w[4*qq + 0], v.x, a0);
            a1 = fmaf(w[4*qq + 1], v.y, a1);
            a2 = fmaf(w[4*qq + 2], v.z, a2);
            a3 = fmaf(w[4*qq + 3], v.w, a3);
        }
        float acc = (a0 + a1) + (a2 + a3);
        acc += __shfl_xor_sync(0xffffffffu, acc, 1);
        if (half == 0) gates_sm[row] = acc;
        __syncthreads();          // gates ready

        if (tid < 32) {           // warp 0: epilogue + senders
            float gi = gates_sm[tid]      + k0v;
            float gf = gates_sm[32 + tid] + k1v;
            float gg = gates_sm[64 + tid] + k2v;
            float go = gates_sm[96 + tid] + k3v;
            float iv = sig_fast(gi), fv = sig_fast(gf);
            float gv = tanh_fast(gg), ov = sig_fast(go);
            float c_new = fv * c_reg + iv * gv;
            float h_new = ov * tanh_fast(c_new);
            c_reg = c_new;
            const int j = 32 * (int)rank + tid;
            if (write_cs) out[step * 128 + j] = c_new;
            g_cs[step * 128 + j] = c_new;
            stage[tid]      = c_new;
            stage[32 + tid] = h_new;
            __syncwarp();
            if (step < STEPS - 1) {
                const unsigned long long* sg = (const unsigned long long*)stage;
                unsigned long long val = sg[tid];   // lane<16: c pair; else h pair
                const int pn = p ^ 1;
                #pragma unroll
                for (int r = 0; r < 4; ++r) {
                    asm volatile("st.shared::cluster.b64 [%0], %1;"
                                 :: "r"(rbase[pn][r]), "l"(val) : "memory");
                }
            }
        }
        // HW cluster barrier: releases warp0's remote stores, acquires peers'
        cluster_sync_all();
    }
}

// ============================================================================
// K2: persistent scorer — R8 winner VERBATIM (88us measured 3x).
//     148 CTAs x 256 threads; F-buffer register prefetch of next tile;
//     bf16 3-segment mma.sync; running register argmax across all tiles.
// ============================================================================
__global__ void __launch_bounds__(256, 1)
k2_score(const float* __restrict__ embed, float* __restrict__ out, int out_size) {
    __shared__ uint4 sbfrag[2048];                  // [nc*8+kc][lane], 32KB
    __shared__ unsigned long long wb[8][STEPS];
    __shared__ int is_last;

    const int tid  = threadIdx.x;
    const int lane = tid & 31;
    const int w    = tid >> 5;
    const int q    = lane & 3;          // col-quad within fragment
    const int r4   = lane >> 2;         // fragment row 0..7

    // ---- build B fragments from g_cs into smem (once per CTA) ----
    {
        const float2* c2 = (const float2*)g_cs;
        #pragma unroll
        for (int it = 0; it < 8; ++it) {
            int idx  = tid + it * 256;
            int ln   = idx & 31;
            int kc   = (idx >> 5) & 7;
            int nc   = idx >> 8;
            int n    = nc * 8 + (ln >> 2);
            int qq   = ln & 3;
            float2 p01 = c2[n * 64 + kc * 8 + qq];
            float2 p23 = c2[n * 64 + kc * 8 + qq + 4];
            uint32_t h01, l01, h23, l23;
            split2(p01, h01, l01);
            split2(p23, h23, l23);
            sbfrag[idx] = make_uint4(h01, h23, l01, l23);
        }
    }
    __syncthreads();

    const float2* e2 = (const float2*)embed;
    float2 F[32];                       // raw A prefetch buffer (64 regs)

#define PREFETCH_TILE(TT) do {                                                 \
    int _r0 = (TT) * 128 + w * 16 + r4;                                        \
    int _r1 = _r0 + 8;                                                         \
    size_t _b0 = (size_t)((_r0 < VOCAB) ? _r0 : 0) * 64;                       \
    size_t _b1 = (size_t)((_r1 < VOCAB) ? _r1 : 0) * 64;                       \
    _Pragma("unroll")                                                          \
    for (int kc = 0; kc < 8; ++kc) {                                           \
        F[kc * 4 + 0] = e2[_b0 + kc * 8 + q];                                  \
        F[kc * 4 + 1] = e2[_b1 + kc * 8 + q];                                  \
        F[kc * 4 + 2] = e2[_b0 + kc * 8 + q + 4];                              \
        F[kc * 4 + 3] = e2[_b1 + kc * 8 + q + 4];                              \
    } } while (0)

    float bs[16]; int br[16];
    #pragma unroll
    for (int i = 0; i < 16; ++i) { bs[i] = -FLT_MAX; br[i] = 0; }

    int t = blockIdx.x;
    if (t < NTILES) PREFETCH_TILE(t);

    while (t < NTILES) {
        const int  row0 = t * 128 + w * 16 + r4;
        const int  row1 = row0 + 8;
        const bool v0 = row0 < VOCAB, v1 = row1 < VOCAB;

        uint32_t aH[8][4], aL[8][4];
        float ssq0 = 0.f, ssq1 = 0.f;
        const float2 z2 = make_float2(0.f, 0.f);
        #pragma unroll
        for (int kc = 0; kc < 8; ++kc) {
            float2 f00 = v0 ? F[kc * 4 + 0] : z2;
            float2 f10 = v1 ? F[kc * 4 + 1] : z2;
            float2 f01 = v0 ? F[kc * 4 + 2] : z2;
            float2 f11 = v1 ? F[kc * 4 + 3] : z2;
            ssq0 = fmaf(f00.x, f00.x, fmaf(f00.y, f00.y,
                    fmaf(f01.x, f01.x, fmaf(f01.y, f01.y, ssq0))));
            ssq1 = fmaf(f10.x, f10.x, fmaf(f10.y, f10.y,
                    fmaf(f11.x, f11.x, fmaf(f11.y, f11.y, ssq1))));
            split2(f00, aH[kc][0], aL[kc][0]);
            split2(f10, aH[kc][1], aL[kc][1]);
            split2(f01, aH[kc][2], aL[kc][2]);
            split2(f11, aH[kc][3], aL[kc][3]);
        }
        ssq0 += __shfl_xor_sync(0xffffffffu, ssq0, 1);
        ssq0 += __shfl_xor_sync(0xffffffffu, ssq0, 2);
        ssq1 += __shfl_xor_sync(0xffffffffu, ssq1, 1);
        ssq1 += __shfl_xor_sync(0xffffffffu, ssq1, 2);
        const float iv0 = 1.0f / fmaxf(sqrtf(ssq0), 1e-8f);
        const float iv1 = 1.0f / fmaxf(sqrtf(ssq1), 1e-8f);

        const int tn = t + K2CTAS;
        if (tn < NTILES) PREFETCH_TILE(tn);

        #pragma unroll
        for (int nc = 0; nc < 8; ++nc) {
            float c1[4]  = {0.f, 0.f, 0.f, 0.f};
            float c2a[4] = {0.f, 0.f, 0.f, 0.f};
            float c3[4]  = {0.f, 0.f, 0.f, 0.f};
            #pragma unroll
            for (int kc = 0; kc < 8; ++kc) {
                uint4 bb = sbfrag[(nc * 8 + kc) * 32 + lane];
                mma16816(c1,  aH[kc], bb.x, bb.y);   // hi*hi
                mma16816(c2a, aH[kc], bb.z, bb.w);   // hi*lo
                mma16816(c3,  aL[kc], bb.x, bb.y);   // lo*hi
            }
            #pragma unroll
            for (int e = 0; e < 2; ++e) {
                const int sl = nc * 2 + e;
                float s0 = v0 ? (c1[e]     + c2a[e]     + c3[e])     * iv0 : -FLT_MAX;
                float s1 = v1 ? (c1[2 + e] + c2a[2 + e] + c3[2 + e]) * iv1 : -FLT_MAX;
                if (s0 > bs[sl]) { bs[sl] = s0; br[sl] = row0; }
                if (s1 > bs[sl]) { bs[sl] = s1; br[sl] = row1; }
            }
        }
        t = tn;        // no barrier: warps free-run across tiles
    }

    // ---- single final reduction ----
    #pragma unroll
    for (int sl = 0; sl < 16; ++sl) {
        unsigned long long key =
            ((unsigned long long)enc_f32(bs[sl]) << 32) |
            (uint32_t)(~(uint32_t)br[sl]);
        #pragma unroll
        for (int off = 4; off < 32; off <<= 1) {
            unsigned long long o = __shfl_xor_sync(0xffffffffu, key, off);
            if (o > key) key = o;
        }
        if (r4 == 0) wb[w][(sl >> 1) * 8 + 2 * q + (sl & 1)] = key;
    }
    __syncthreads();
    if (tid < STEPS) {
        unsigned long long best = wb[0][tid];
        #pragma unroll
        for (int ww = 1; ww < 8; ++ww)
            if (wb[ww][tid] > best) best = wb[ww][tid];
        atomicMax(&g_best[tid], best);
    }

    // ---- last CTA decodes token ids ----
    __threadfence();
    __syncthreads();
    if (tid == 0) {
        int c = atomicAdd(&g_done, 1);
        is_last = (c == (int)gridDim.x - 1);
    }
    __syncthreads();
    if (is_last) {
        if (tid == 0) g_done = 0;
        __threadfence();
        if (tid < STEPS) {
            uint32_t idx = ~((uint32_t)(g_best[tid] & 0xffffffffu));
            out[(out_size - STEPS) + tid] = (float)idx;
        }
    }
#undef PREFETCH_TILE
}

// ============================================================================
extern "C" void kernel_launch(void* const* d_in, const int* in_sizes, int n_in,
                              void* d_out, int out_size) {
    const float* inp   = (const float*)d_in[0];
    const float* embed = (const float*)d_in[1];
    const float* w_ih  = (const float*)d_in[2];
    const float* w_hh  = (const float*)d_in[3];
    const float* b_ih  = (const float*)d_in[4];
    const float* b_hh  = (const float*)d_in[5];
    float* out = (float*)d_out;
    (void)in_sizes; (void)n_in;

    const int write_cs = (out_size >= STEPS * 128 + STEPS) ? 1 : 0;

    // Phase A: cluster-of-4 LSTM
    {
        cudaLaunchConfig_t cfg = {};
        cfg.gridDim  = dim3(4, 1, 1);
        cfg.blockDim = dim3(256, 1, 1);
        cfg.dynamicSmemBytes = 0;
        cfg.stream = 0;
        cudaLaunchAttribute attrs[1];
        attrs[0].id = cudaLaunchAttributeClusterDimension;
        attrs[0].val.clusterDim.x = 4;
        attrs[0].val.clusterDim.y = 1;
        attrs[0].val.clusterDim.z = 1;
        cfg.attrs = attrs;
        cfg.numAttrs = 1;
        cudaLaunchKernelEx(&cfg, k1_lstm, embed, w_ih, w_hh, inp, b_ih, b_hh,
                           out, write_cs);
    }

    // Phase B: persistent mma.sync scoring + argmax + decode (R8 winner)
    k2_score<<<K2CTAS, 256>>>(embed, out, out_size);
}